// round 10
// baseline (speedup 1.0000x reference)
#include <cuda_runtime.h>

// Problem constants (fixed by setup_inputs)
#define B_     8
#define N_     3072
#define D_     1024
#define D4_    256          // D/4 (float4)
#define STEPS  1024         // N/POOL
#define POOL_  3
#define NCH    128          // chunks per batch
#define CWIN   8            // windows per chunk
#define EPS_   0.006f

// Scratch (__device__ globals; no allocations allowed)
__device__ float g_L [(size_t)B_ * (STEPS + 1) * D_];  // chunk-local exclusive window prefix
__device__ float g_S [(size_t)B_ * NCH * D_];          // chunk totals
__device__ float g_SP[(size_t)B_ * (NCH + 1) * D_];    // exclusive scan of chunk totals
__device__ int   g_is32;                               // 1 if graph is int32

__device__ __forceinline__ float4 f4add(float4 a, float4 b) {
    return make_float4(a.x + b.x, a.y + b.y, a.z + b.z, a.w + b.w);
}
__device__ __forceinline__ float4 f4sub(float4 a, float4 b) {
    return make_float4(a.x - b.x, a.y - b.y, a.z - b.z, a.w - b.w);
}
__device__ __forceinline__ float4 ldcs4(const float4* p) { return __ldcs(p); }
__device__ __forceinline__ void stcs4(float4* p, float4 v) { __stcs(p, v); }

// ---------------------------------------------------------------------------
// 1) Fused pass over x (streamed): window means -> out odd rows (streamed),
//    chunk-local exclusive prefix -> L (L2-resident), chunk total -> S.
//    Grid = B*NCH = 1024 blocks (8 windows each) for ~86% occupancy.
//    Block 0 additionally runs the graph-dtype detection and writes g_is32.
// ---------------------------------------------------------------------------
__global__ void __launch_bounds__(256) k_fused(const float4* __restrict__ x,
                                               const unsigned int* __restrict__ g32,
                                               float4* __restrict__ out) {
    __shared__ unsigned int sh[256];
    int blk = blockIdx.x;               // B*NCH = 1024 blocks
    int b = blk >> 7, c = blk & 127;
    int q0 = c * CWIN;
    int i = threadIdx.x;

    const float4* xr = x + ((size_t)(b * N_ + POOL_ * q0)) * D4_ + i;
    float4* L4 = (float4*)g_L + ((size_t)b * (STEPS + 1) + q0) * D4_ + i;
    float4* o4 = out + ((size_t)(b * 2 * STEPS) + 2 * q0 + 1) * D4_ + i;

    const float inv3 = 1.0f / 3.0f;
    float4 run = make_float4(0.f, 0.f, 0.f, 0.f);
#pragma unroll
    for (int w = 0; w < CWIN; w++) {
        float4 a  = ldcs4(&xr[(size_t)(3 * w)     * D4_]);
        float4 bb = ldcs4(&xr[(size_t)(3 * w + 1) * D4_]);
        float4 cc = ldcs4(&xr[(size_t)(3 * w + 2) * D4_]);
        L4[(size_t)w * D4_] = run;                       // keep in L2
        float4 sum = f4add(f4add(a, bb), cc);            // raw row-sum
        stcs4(&o4[(size_t)(2 * w) * D4_],
              make_float4(sum.x * inv3, sum.y * inv3, sum.z * inv3, sum.w * inv3));
        run = f4add(run, sum);
    }
    ((float4*)g_S)[((size_t)b * NCH + c) * D4_ + i] = run;

    // --- block 0 only: dtype detection over 1024 sampled entries -----------
    if (blk == 0) {
        unsigned int v = 0;
#pragma unroll
        for (int k = 0; k < 4; k++) v |= g32[2 * (k * 256 + i) + 1];
        sh[i] = v;
        __syncthreads();
        for (int o = 128; o > 0; o >>= 1) {
            if (i < o) sh[i] |= sh[i + o];
            __syncthreads();
        }
        if (i == 0) g_is32 = (sh[0] != 0u) ? 1 : 0;
    }
}

// ---------------------------------------------------------------------------
// 2) Hierarchical scan of 128 chunk totals, spill-free.
//    Grid: 512 blocks = b(8) x d-tile(64 of 16 d). Block: 16 d-lanes x 16
//    groups; each thread sums 8 chunks (regs, MLP=8), shared 16-way exclusive
//    scan per d-lane, then emits its 8 SP entries.
// ---------------------------------------------------------------------------
__global__ void __launch_bounds__(256) k_scan() {
    __shared__ float sh[16][16];
    int blk = blockIdx.x;               // 512 blocks
    int b = blk >> 6, dt = blk & 63;
    int dl = threadIdx.x & 15;          // d-lane within tile
    int gr = threadIdx.x >> 4;          // chunk group 0..15
    int d = dt * 16 + dl;

    const float* S = g_S + (size_t)b * NCH * D_ + d;
    float v[8];
#pragma unroll
    for (int j = 0; j < 8; j++) v[j] = S[(size_t)(gr * 8 + j) * D_];
    float gsum = ((v[0] + v[1]) + (v[2] + v[3])) + ((v[4] + v[5]) + (v[6] + v[7]));
    sh[gr][dl] = gsum;
    __syncthreads();

    float off = 0.f;
#pragma unroll
    for (int j = 0; j < 16; j++) { float t = sh[j][dl]; if (j < gr) off += t; }

    float* SPp = g_SP + (size_t)b * (NCH + 1) * D_ + d;
    float run = off;
#pragma unroll
    for (int j = 0; j < 8; j++) {
        SPp[(size_t)(gr * 8 + j) * D_] = run;
        run += v[j];
    }
    if (gr == 15) {
        SPp[(size_t)NCH * D_] = run;                              // SP[128] = total
        g_L[((size_t)b * (STEPS + 1) + STEPS) * D_ + d] = 0.f;    // L[q=STEPS] = 0
    }
}

// ---------------------------------------------------------------------------
// 3) Gather with inline index prep (ceiling trick):
//    boundary k=3q+r: r==0 -> (q, none); r==1 -> (q, +x[3q]); r==2 -> (q+1, -x[3q+2])
//    acc = (L[qe]+SP[qe>>3]) - (L[qs]+SP[qs>>3]) +/- residual x rows.
// ---------------------------------------------------------------------------
__global__ void __launch_bounds__(256) k_gather(const float4* __restrict__ x,
                                                const void* __restrict__ graph,
                                                float4* __restrict__ out) {
    int bt = blockIdx.x;
    int b = bt >> 10;
    int i = threadIdx.x;

    int s, e;
    if (g_is32) {
        int2 v = ((const int2*)graph)[bt];
        s = v.x; e = v.y;
    } else {
        longlong2 v = ((const longlong2*)graph)[bt];
        s = (int)v.x; e = (int)v.y;
    }
    int ke = e + 1, ks = s;
    int qe = ke / 3, re = ke - 3 * qe, resE = 0;       // end boundary (added)
    if (re == 1) resE = (3 * qe) + 1;                                  // + x[3q]
    else if (re == 2) { qe += 1; resE = -((3 * (qe - 1) + 2) + 1); }   // - x[3q+2]
    int qs = ks / 3, rs = ks - 3 * qs, resS = 0;       // start boundary (subtracted)
    if (rs == 1) resS = -((3 * qs) + 1);                               // - x[3q]
    else if (rs == 2) { qs += 1; resS = (3 * (qs - 1) + 2) + 1; }      // + x[3q+2]
    float invlen = 1.0f / (float)(ke - ks);

    const float4* L4  = (const float4*)g_L  + (size_t)b * (STEPS + 1) * D4_;
    const float4* SP4 = (const float4*)g_SP + (size_t)b * (NCH + 1) * D4_;
    const float4* x4  = x + (size_t)b * N_ * D4_;

    float4 pe = f4add(L4[(size_t)qe * D4_ + i], SP4[(size_t)(qe >> 3) * D4_ + i]);
    float4 ps = f4add(L4[(size_t)qs * D4_ + i], SP4[(size_t)(qs >> 3) * D4_ + i]);
    float4 acc = f4sub(pe, ps);

    if (resE != 0) {
        int row = (resE > 0 ? resE : -resE) - 1;
        float sgn = (resE > 0) ? 1.f : -1.f;
        float4 v = ldcs4(&x4[(size_t)row * D4_ + i]);
        acc = make_float4(fmaf(sgn, v.x, acc.x), fmaf(sgn, v.y, acc.y),
                          fmaf(sgn, v.z, acc.z), fmaf(sgn, v.w, acc.w));
    }
    if (resS != 0) {
        int row = (resS > 0 ? resS : -resS) - 1;
        float sgn = (resS > 0) ? 1.f : -1.f;
        float4 v = ldcs4(&x4[(size_t)row * D4_ + i]);
        acc = make_float4(fmaf(sgn, v.x, acc.x), fmaf(sgn, v.y, acc.y),
                          fmaf(sgn, v.z, acc.z), fmaf(sgn, v.w, acc.w));
    }

    float4 o = make_float4(acc.x * invlen + EPS_, acc.y * invlen + EPS_,
                           acc.z * invlen + EPS_, acc.w * invlen + EPS_);
    stcs4(&out[(size_t)(2 * bt) * D4_ + i], o);
}

// ---------------------------------------------------------------------------
extern "C" void kernel_launch(void* const* d_in, const int* in_sizes, int n_in,
                              void* d_out, int out_size) {
    const float* x     = (const float*)d_in[0];
    const void*  graph = d_in[1];
    float*       out   = (float*)d_out;

    k_fused <<<B_ * NCH, 256>>>((const float4*)x, (const unsigned int*)graph,
                                (float4*)out);
    k_scan  <<<512, 256>>>();
    k_gather<<<B_ * STEPS, 256>>>((const float4*)x, graph, (float4*)out);
}

// round 11
// speedup vs baseline: 1.2180x; 1.2180x over previous
#include <cuda_runtime.h>

// Problem constants (fixed by setup_inputs)
#define B_     8
#define N_     3072
#define D_     1024
#define D4_    256          // D/4 (float4)
#define STEPS  1024         // N/POOL
#define POOL_  3
#define NCH    64           // chunks per batch
#define CWIN   16           // windows per chunk
#define EPS_   0.006f

// Scratch (__device__ globals; no allocations allowed)
__device__ float g_L [(size_t)B_ * (STEPS + 1) * D_];  // chunk-local exclusive window prefix
__device__ float g_S [(size_t)B_ * NCH * D_];          // chunk totals
__device__ float g_SP[(size_t)B_ * (NCH + 1) * D_];    // exclusive scan of chunk totals
__device__ int   g_is32;                               // 1 if graph is int32

__device__ __forceinline__ float4 f4add(float4 a, float4 b) {
    return make_float4(a.x + b.x, a.y + b.y, a.z + b.z, a.w + b.w);
}
__device__ __forceinline__ float4 f4sub(float4 a, float4 b) {
    return make_float4(a.x - b.x, a.y - b.y, a.z - b.z, a.w - b.w);
}
__device__ __forceinline__ float4 ldcs4(const float4* p) { return __ldcs(p); }
__device__ __forceinline__ void stcs4(float4* p, float4 v) { __stcs(p, v); }

// ---------------------------------------------------------------------------
// 1) Fused pass over x (streamed) with DEPTH-2 SOFTWARE PIPELINE:
//    window means -> out odd rows (streamed), chunk-local exclusive prefix
//    -> L (L2-resident), chunk total -> S. Grid = B*NCH = 512 blocks
//    (round-9 proven shape). Block 0 also runs graph-dtype detection.
// ---------------------------------------------------------------------------
__global__ void __launch_bounds__(256) k_fused(const float4* __restrict__ x,
                                               const unsigned int* __restrict__ g32,
                                               float4* __restrict__ out) {
    __shared__ unsigned int sh[256];
    int blk = blockIdx.x;               // B*NCH = 512 blocks
    int b = blk >> 6, c = blk & 63;
    int q0 = c * CWIN;
    int i = threadIdx.x;

    const float4* xr = x + ((size_t)(b * N_ + POOL_ * q0)) * D4_ + i;
    float4* L4 = (float4*)g_L + ((size_t)b * (STEPS + 1) + q0) * D4_ + i;
    float4* o4 = out + ((size_t)(b * 2 * STEPS) + 2 * q0 + 1) * D4_ + i;

    const float inv3 = 1.0f / 3.0f;
    float4 run = make_float4(0.f, 0.f, 0.f, 0.f);

    // pipeline prologue: windows 0 and 1 in flight
    float4 A0 = ldcs4(&xr[0]);
    float4 B0 = ldcs4(&xr[(size_t)1 * D4_]);
    float4 C0 = ldcs4(&xr[(size_t)2 * D4_]);
    float4 A1 = ldcs4(&xr[(size_t)3 * D4_]);
    float4 B1 = ldcs4(&xr[(size_t)4 * D4_]);
    float4 C1 = ldcs4(&xr[(size_t)5 * D4_]);

#pragma unroll
    for (int w = 0; w < CWIN; w++) {
        float4 A2, B2, C2;
        if (w + 2 < CWIN) {                  // prefetch window w+2
            A2 = ldcs4(&xr[(size_t)(3 * (w + 2))     * D4_]);
            B2 = ldcs4(&xr[(size_t)(3 * (w + 2) + 1) * D4_]);
            C2 = ldcs4(&xr[(size_t)(3 * (w + 2) + 2) * D4_]);
        }
        L4[(size_t)w * D4_] = run;                       // keep in L2
        float4 sum = f4add(f4add(A0, B0), C0);           // raw row-sum
        stcs4(&o4[(size_t)(2 * w) * D4_],
              make_float4(sum.x * inv3, sum.y * inv3, sum.z * inv3, sum.w * inv3));
        run = f4add(run, sum);
        A0 = A1; B0 = B1; C0 = C1;
        A1 = A2; B1 = B2; C1 = C2;
    }
    ((float4*)g_S)[((size_t)b * NCH + c) * D4_ + i] = run;

    // --- block 0 only: dtype detection over 1024 sampled entries -----------
    if (blk == 0) {
        unsigned int v = 0;
#pragma unroll
        for (int k = 0; k < 4; k++) v |= g32[2 * (k * 256 + i) + 1];
        sh[i] = v;
        __syncthreads();
        for (int o = 128; o > 0; o >>= 1) {
            if (i < o) sh[i] |= sh[i + o];
            __syncthreads();
        }
        if (i == 0) g_is32 = (sh[0] != 0u) ? 1 : 0;
    }
}

// ---------------------------------------------------------------------------
// 2) Hierarchical scan of 64 chunk totals, widened: 512 blocks.
//    Grid: 512 = b(8) x d-tile(64 of 16 d). Block: 16 d-lanes x 16 groups;
//    each thread sums 4 chunks (regs, MLP=4), shared 16-way exclusive scan
//    per d-lane, then emits its 4 SP entries.
// ---------------------------------------------------------------------------
__global__ void __launch_bounds__(256) k_scan() {
    __shared__ float sh[16][16];
    int blk = blockIdx.x;               // 512 blocks
    int b = blk >> 6, dt = blk & 63;
    int dl = threadIdx.x & 15;          // d-lane within tile
    int gr = threadIdx.x >> 4;          // chunk group 0..15
    int d = dt * 16 + dl;

    const float* S = g_S + (size_t)b * NCH * D_ + d;
    float v[4];
#pragma unroll
    for (int j = 0; j < 4; j++) v[j] = S[(size_t)(gr * 4 + j) * D_];
    float gsum = (v[0] + v[1]) + (v[2] + v[3]);
    sh[gr][dl] = gsum;
    __syncthreads();

    float off = 0.f;
#pragma unroll
    for (int j = 0; j < 16; j++) { float t = sh[j][dl]; if (j < gr) off += t; }

    float* SPp = g_SP + (size_t)b * (NCH + 1) * D_ + d;
    float run = off;
#pragma unroll
    for (int j = 0; j < 4; j++) {
        SPp[(size_t)(gr * 4 + j) * D_] = run;
        run += v[j];
    }
    if (gr == 15) {
        SPp[(size_t)NCH * D_] = run;                              // SP[64] = total
        g_L[((size_t)b * (STEPS + 1) + STEPS) * D_ + d] = 0.f;    // L[q=STEPS] = 0
    }
}

// ---------------------------------------------------------------------------
// 3) Gather with inline index prep (ceiling trick):
//    boundary k=3q+r: r==0 -> (q, none); r==1 -> (q, +x[3q]); r==2 -> (q+1, -x[3q+2])
//    acc = (L[qe]+SP[qe>>4]) - (L[qs]+SP[qs>>4]) +/- residual x rows.
// ---------------------------------------------------------------------------
__global__ void __launch_bounds__(256) k_gather(const float4* __restrict__ x,
                                                const void* __restrict__ graph,
                                                float4* __restrict__ out) {
    int bt = blockIdx.x;
    int b = bt >> 10;
    int i = threadIdx.x;

    int s, e;
    if (g_is32) {
        int2 v = ((const int2*)graph)[bt];
        s = v.x; e = v.y;
    } else {
        longlong2 v = ((const longlong2*)graph)[bt];
        s = (int)v.x; e = (int)v.y;
    }
    int ke = e + 1, ks = s;
    int qe = ke / 3, re = ke - 3 * qe, resE = 0;       // end boundary (added)
    if (re == 1) resE = (3 * qe) + 1;                                  // + x[3q]
    else if (re == 2) { qe += 1; resE = -((3 * (qe - 1) + 2) + 1); }   // - x[3q+2]
    int qs = ks / 3, rs = ks - 3 * qs, resS = 0;       // start boundary (subtracted)
    if (rs == 1) resS = -((3 * qs) + 1);                               // - x[3q]
    else if (rs == 2) { qs += 1; resS = (3 * (qs - 1) + 2) + 1; }      // + x[3q+2]
    float invlen = 1.0f / (float)(ke - ks);

    const float4* L4  = (const float4*)g_L  + (size_t)b * (STEPS + 1) * D4_;
    const float4* SP4 = (const float4*)g_SP + (size_t)b * (NCH + 1) * D4_;
    const float4* x4  = x + (size_t)b * N_ * D4_;

    float4 pe = f4add(L4[(size_t)qe * D4_ + i], SP4[(size_t)(qe >> 4) * D4_ + i]);
    float4 ps = f4add(L4[(size_t)qs * D4_ + i], SP4[(size_t)(qs >> 4) * D4_ + i]);
    float4 acc = f4sub(pe, ps);

    if (resE != 0) {
        int row = (resE > 0 ? resE : -resE) - 1;
        float sgn = (resE > 0) ? 1.f : -1.f;
        float4 v = ldcs4(&x4[(size_t)row * D4_ + i]);
        acc = make_float4(fmaf(sgn, v.x, acc.x), fmaf(sgn, v.y, acc.y),
                          fmaf(sgn, v.z, acc.z), fmaf(sgn, v.w, acc.w));
    }
    if (resS != 0) {
        int row = (resS > 0 ? resS : -resS) - 1;
        float sgn = (resS > 0) ? 1.f : -1.f;
        float4 v = ldcs4(&x4[(size_t)row * D4_ + i]);
        acc = make_float4(fmaf(sgn, v.x, acc.x), fmaf(sgn, v.y, acc.y),
                          fmaf(sgn, v.z, acc.z), fmaf(sgn, v.w, acc.w));
    }

    float4 o = make_float4(acc.x * invlen + EPS_, acc.y * invlen + EPS_,
                           acc.z * invlen + EPS_, acc.w * invlen + EPS_);
    stcs4(&out[(size_t)(2 * bt) * D4_ + i], o);
}

// ---------------------------------------------------------------------------
extern "C" void kernel_launch(void* const* d_in, const int* in_sizes, int n_in,
                              void* d_out, int out_size) {
    const float* x     = (const float*)d_in[0];
    const void*  graph = d_in[1];
    float*       out   = (float*)d_out;

    k_fused <<<B_ * NCH, 256>>>((const float4*)x, (const unsigned int*)graph,
                                (float4*)out);
    k_scan  <<<512, 256>>>();
    k_gather<<<B_ * STEPS, 256>>>((const float4*)x, graph, (float4*)out);
}